// round 6
// baseline (speedup 1.0000x reference)
#include <cuda_runtime.h>
#include <cuda_bf16.h>

#define N_NODES 100000
#define N_EDGES 1280000
#define HH 64
#define NL 5
#define N_GRAPHS 512

typedef unsigned long long ull;

// ---------------- static device scratch ----------------
__device__ __align__(16) float d_z[N_NODES * HH];
__device__ __align__(16) float d_hin[N_NODES * HH];
__device__ __align__(16) float d_h1[N_NODES * 128];
__device__ __align__(16) float d_h2[N_NODES * HH];
__device__ __align__(16) float d_tab[512 * HH];
__device__ int d_counts[N_NODES];            // statically zero; re-zeroed by fill each run
__device__ int d_rowstart[N_NODES + 1];
__device__ int d_cursor[N_NODES];
__device__ unsigned int d_csr_pack[N_EDGES]; // src | (code<<17)
__device__ unsigned short d_code[N_EDGES];
__device__ float d_s1sum[128], d_s1sq[128];
__device__ float d_s2sum[64],  d_s2sq[64];

// ---------------- packed f32x2 helpers ----------------
__device__ __forceinline__ ull pack2(float x, float y) {
    ull r; asm("mov.b64 %0, {%1, %2};" : "=l"(r) : "f"(x), "f"(y)); return r;
}
__device__ __forceinline__ void unpack2(ull v, float &x, float &y) {
    asm("mov.b64 {%0, %1}, %2;" : "=f"(x), "=f"(y) : "l"(v));
}
__device__ __forceinline__ void fma2u(ull &d, ull a, ull b) {
    asm("fma.rn.f32x2 %0, %1, %2, %0;" : "+l"(d) : "l"(a), "l"(b));
}

// ---------------- fused setup: z0 + bond table + degree count ----------------
__global__ void __launch_bounds__(256) setup_kernel(const int* __restrict__ x,
                                                    const float* __restrict__ atom_emb,
                                                    const float* __restrict__ bond_emb,
                                                    const int* __restrict__ ei,
                                                    const int* __restrict__ ea) {
    int bb = blockIdx.x;
    if (bb < 25000) {
        int t = bb * 256 + threadIdx.x;  // N*64
        int n = t >> 6, c = t & 63;
        float s = 0.f;
#pragma unroll
        for (int a = 0; a < 9; a++) {
            int idx = __ldg(&x[n * 9 + a]);
            s += __ldg(&atom_emb[(a * 128 + idx) * HH + c]);
        }
        d_z[t] = s;
    } else if (bb < 25128) {
        int t = (bb - 25000) * 256 + threadIdx.x;  // 512*64
        int q = t >> 6, c = t & 63;
        int a0 = q >> 6, a1 = (q >> 3) & 7, a2 = q & 7;
        d_tab[t] = bond_emb[a0 * HH + c] + bond_emb[(8 + a1) * HH + c] + bond_emb[(16 + a2) * HH + c];
    } else {
        int e = (bb - 25128) * 256 + threadIdx.x;  // N_EDGES
        int a0 = ea[e * 3 + 0], a1 = ea[e * 3 + 1], a2 = ea[e * 3 + 2];
        d_code[e] = (unsigned short)((a0 << 6) | (a1 << 3) | a2);
        atomicAdd(&d_counts[ei[N_EDGES + e]], 1);
    }
}

// single-block scan, 4 elements per thread per pass (25 passes)
__global__ void scan_kernel() {
    __shared__ int wsum[32];
    __shared__ int s_carry;
    int tid = threadIdx.x, lane = tid & 31, wid = tid >> 5;
    if (tid == 0) s_carry = 0;
    __syncthreads();
    for (int base = 0; base < N_NODES; base += 4096) {
        int i0 = base + tid * 4;
        int4 v = make_int4(0, 0, 0, 0);
        if (i0 + 3 < N_NODES) v = *(const int4*)&d_counts[i0];
        else {
            if (i0 + 0 < N_NODES) v.x = d_counts[i0 + 0];
            if (i0 + 1 < N_NODES) v.y = d_counts[i0 + 1];
            if (i0 + 2 < N_NODES) v.z = d_counts[i0 + 2];
            if (i0 + 3 < N_NODES) v.w = d_counts[i0 + 3];
        }
        int t0 = v.x, t1 = t0 + v.y, t2 = t1 + v.z, t3 = t2 + v.w;  // inclusive within thread
        int xs = t3;
#pragma unroll
        for (int o = 1; o < 32; o <<= 1) { int y = __shfl_up_sync(0xffffffffu, xs, o); if (lane >= o) xs += y; }
        if (lane == 31) wsum[wid] = xs;
        __syncthreads();
        if (wid == 0) {
            int s = wsum[lane];
#pragma unroll
            for (int o = 1; o < 32; o <<= 1) { int y = __shfl_up_sync(0xffffffffu, s, o); if (lane >= o) s += y; }
            wsum[lane] = s;
        }
        __syncthreads();
        int warp_excl = (wid > 0) ? wsum[wid - 1] : 0;
        int carry = s_carry;
        int ex = carry + warp_excl + xs - t3;   // exclusive prefix for this thread's first elem
        int4 rs = make_int4(ex, ex + t0, ex + t1, ex + t2);
        if (i0 + 3 < N_NODES) {
            *(int4*)&d_rowstart[i0] = rs;
            *(int4*)&d_cursor[i0] = rs;
        } else {
            if (i0 + 0 < N_NODES) { d_rowstart[i0 + 0] = rs.x; d_cursor[i0 + 0] = rs.x; }
            if (i0 + 1 < N_NODES) { d_rowstart[i0 + 1] = rs.y; d_cursor[i0 + 1] = rs.y; }
            if (i0 + 2 < N_NODES) { d_rowstart[i0 + 2] = rs.z; d_cursor[i0 + 2] = rs.z; }
            if (i0 + 3 < N_NODES) { d_rowstart[i0 + 3] = rs.w; d_cursor[i0 + 3] = rs.w; }
        }
        __syncthreads();
        if (tid == 1023) s_carry = carry + wsum[31];
        __syncthreads();
    }
    if (threadIdx.x == 0) d_rowstart[N_NODES] = s_carry;
}

// fill CSR (packed src|code<<17); trailing blocks re-zero d_counts for the NEXT execution
__global__ void fill_kernel(const int* __restrict__ ei) {
    int bb = blockIdx.x;
    if (bb < 5000) {
        int e = bb * 256 + threadIdx.x;
        int dst = ei[N_EDGES + e];
        int pos = atomicAdd(&d_cursor[dst], 1);
        d_csr_pack[pos] = (unsigned int)ei[e] | ((unsigned int)d_code[e] << 17);
    } else {
        int t = (bb - 5000) * 256 + threadIdx.x;
        if (t < N_NODES) d_counts[t] = 0;
    }
}

// ---------------- per-layer kernels ----------------
// one warp per node, 4 edges in flight (8-lane groups x 8 cols), predicate-free body + tail
__global__ void __launch_bounds__(256) agg_kernel() {
    if (blockIdx.x == 0) {
        int t = threadIdx.x;
        if (t < 128) { d_s1sum[t] = 0.f; d_s1sq[t] = 0.f; }
        else if (t < 192) { int c = t - 128; d_s2sum[c] = 0.f; d_s2sq[c] = 0.f; }
    }
    int node = (blockIdx.x * blockDim.x + threadIdx.x) >> 5;
    int lane = threadIdx.x & 31;
    if (node >= N_NODES) return;
    int h = lane & 7, g = lane >> 3;
    float4 a0 = make_float4(0.f, 0.f, 0.f, 0.f);
    float4 a1 = make_float4(0.f, 0.f, 0.f, 0.f);
    int rs = d_rowstart[node], re = d_rowstart[node + 1];
    for (int base = rs; base < re; base += 32) {
        int cnt = re - base; if (cnt > 32) cnt = 32;
        unsigned int pk = 0;
        if (lane < cnt) pk = d_csr_pack[base + lane];
        int full = cnt >> 2;
        for (int jj = 0; jj < full; jj++) {
            unsigned int v = __shfl_sync(0xffffffffu, pk, 4 * jj + g);
            int s = (int)(v & 0x1FFFFu);
            int c = (int)(v >> 17);
            const float4* zp = (const float4*)(d_z + (size_t)s * HH) + h * 2;
            const float4* tp = (const float4*)(d_tab + c * HH) + h * 2;
            float4 z0 = __ldg(zp), z1 = __ldg(zp + 1);
            float4 t0 = __ldg(tp), t1 = __ldg(tp + 1);
            a0.x += fmaxf(z0.x + t0.x, 0.f); a0.y += fmaxf(z0.y + t0.y, 0.f);
            a0.z += fmaxf(z0.z + t0.z, 0.f); a0.w += fmaxf(z0.w + t0.w, 0.f);
            a1.x += fmaxf(z1.x + t1.x, 0.f); a1.y += fmaxf(z1.y + t1.y, 0.f);
            a1.z += fmaxf(z1.z + t1.z, 0.f); a1.w += fmaxf(z1.w + t1.w, 0.f);
        }
        int rem = cnt & 3;
        if (rem) {
            unsigned int v = __shfl_sync(0xffffffffu, pk, 4 * full + (g & 3) % 4 * 0 + ((g < rem) ? (4 * full + g) - (4 * full) : 0) + 4 * full * 0 + ((4 * full + g) < cnt ? 0 : 0) + (4 * full + ((g < rem) ? g : 0)) - (4 * full));
            // simplified: fetch edge 4*full+min(g,rem-1); inactive groups discard
            v = __shfl_sync(0xffffffffu, pk, 4 * full + ((g < rem) ? g : 0));
            if (g < rem) {
                int s = (int)(v & 0x1FFFFu);
                int c = (int)(v >> 17);
                const float4* zp = (const float4*)(d_z + (size_t)s * HH) + h * 2;
                const float4* tp = (const float4*)(d_tab + c * HH) + h * 2;
                float4 z0 = __ldg(zp), z1 = __ldg(zp + 1);
                float4 t0 = __ldg(tp), t1 = __ldg(tp + 1);
                a0.x += fmaxf(z0.x + t0.x, 0.f); a0.y += fmaxf(z0.y + t0.y, 0.f);
                a0.z += fmaxf(z0.z + t0.z, 0.f); a0.w += fmaxf(z0.w + t0.w, 0.f);
                a1.x += fmaxf(z1.x + t1.x, 0.f); a1.y += fmaxf(z1.y + t1.y, 0.f);
                a1.z += fmaxf(z1.z + t1.z, 0.f); a1.w += fmaxf(z1.w + t1.w, 0.f);
            }
        }
    }
    // reduce across the 4 edge-groups (lane bits 3,4)
#pragma unroll
    for (int o = 8; o <= 16; o <<= 1) {
        a0.x += __shfl_xor_sync(0xffffffffu, a0.x, o);
        a0.y += __shfl_xor_sync(0xffffffffu, a0.y, o);
        a0.z += __shfl_xor_sync(0xffffffffu, a0.z, o);
        a0.w += __shfl_xor_sync(0xffffffffu, a0.w, o);
        a1.x += __shfl_xor_sync(0xffffffffu, a1.x, o);
        a1.y += __shfl_xor_sync(0xffffffffu, a1.y, o);
        a1.z += __shfl_xor_sync(0xffffffffu, a1.z, o);
        a1.w += __shfl_xor_sync(0xffffffffu, a1.w, o);
    }
    if (g == 0) {
        const float4* zp = (const float4*)(d_z + (size_t)node * HH) + h * 2;
        float4 z0 = __ldg(zp), z1 = __ldg(zp + 1);
        a0.x += z0.x; a0.y += z0.y; a0.z += z0.z; a0.w += z0.w;
        a1.x += z1.x; a1.y += z1.y; a1.z += z1.z; a1.w += z1.w;
        float4* op = (float4*)(d_hin + (size_t)node * HH) + h * 2;
        op[0] = a0; op[1] = a1;
    }
}

// ================= GEMM1: h1[128 tile][128] = hin @ W1 + b1, fused col-stats =================
__global__ void __launch_bounds__(256, 2) gemm1_kernel(const float* __restrict__ W, const float* __restrict__ b) {
    extern __shared__ __align__(16) float sm[];
    float* Wsh = sm;             // [64][132]
    float* Ash = sm + 64 * 132;  // [64][132]
    float* bsh = Ash + 64 * 132; // [128]
    int tid = threadIdx.x;
    int nb = blockIdx.x * 128;

    for (int t = tid; t < 8192; t += 256) {
        int k = t >> 7, c = t & 127;
        Wsh[k * 132 + c] = W[t];
    }
    if (tid < 128) bsh[tid] = b[tid];
    for (int t = tid; t < 8192; t += 256) {
        int n = t >> 6, c = t & 63;
        int gn = nb + n;
        Ash[c * 132 + n] = (gn < N_NODES) ? d_hin[(size_t)gn * HH + c] : 0.f;
    }
    __syncthreads();

    int warp = tid >> 5, lane = tid & 31;
    int wr = warp >> 1, wc = warp & 1;
    int tr = lane >> 3, tc = lane & 7;
    int node0 = wr * 32 + tr * 8;
    int col0 = wc * 64 + tc * 8;

    ull acc[8][4];
    {
        float4 b0 = *(const float4*)&bsh[col0];
        float4 b1 = *(const float4*)&bsh[col0 + 4];
        ull i0 = pack2(b0.x, b0.y), i1 = pack2(b0.z, b0.w);
        ull i2 = pack2(b1.x, b1.y), i3 = pack2(b1.z, b1.w);
#pragma unroll
        for (int i = 0; i < 8; i++) { acc[i][0] = i0; acc[i][1] = i1; acc[i][2] = i2; acc[i][3] = i3; }
    }

#pragma unroll 8
    for (int k = 0; k < 64; k++) {
        float4 a0 = *(const float4*)&Ash[k * 132 + node0];
        float4 a1 = *(const float4*)&Ash[k * 132 + node0 + 4];
        ulonglong2 wA = *(const ulonglong2*)&Wsh[k * 132 + col0];
        ulonglong2 wB = *(const ulonglong2*)&Wsh[k * 132 + col0 + 4];
        float an[8] = {a0.x, a0.y, a0.z, a0.w, a1.x, a1.y, a1.z, a1.w};
#pragma unroll
        for (int i = 0; i < 8; i++) {
            ull ai = pack2(an[i], an[i]);
            fma2u(acc[i][0], ai, wA.x);
            fma2u(acc[i][1], ai, wA.y);
            fma2u(acc[i][2], ai, wB.x);
            fma2u(acc[i][3], ai, wB.y);
        }
    }

    float csum[8] = {0,0,0,0,0,0,0,0}, csq[8] = {0,0,0,0,0,0,0,0};
#pragma unroll
    for (int i = 0; i < 8; i++) {
        int node = nb + node0 + i;
        if (node < N_NODES) {
            *(ulonglong2*)&d_h1[(size_t)node * 128 + col0] = make_ulonglong2(acc[i][0], acc[i][1]);
            *(ulonglong2*)&d_h1[(size_t)node * 128 + col0 + 4] = make_ulonglong2(acc[i][2], acc[i][3]);
#pragma unroll
            for (int j = 0; j < 4; j++) {
                float v0, v1; unpack2(acc[i][j], v0, v1);
                csum[2 * j] += v0; csq[2 * j] += v0 * v0;
                csum[2 * j + 1] += v1; csq[2 * j + 1] += v1 * v1;
            }
        }
    }
    __syncthreads();
    int g = wr * 4 + tr;  // 0..15
#pragma unroll
    for (int c = 0; c < 8; c++) {
        Wsh[g * 264 + col0 + c] = csum[c];
        Wsh[g * 264 + 128 + col0 + c] = csq[c];
    }
    __syncthreads();
    {
        float v = 0.f;
#pragma unroll
        for (int gg = 0; gg < 16; gg++) v += Wsh[gg * 264 + tid];
        if (tid < 128) atomicAdd(&d_s1sum[tid], v);
        else atomicAdd(&d_s1sq[tid - 128], v);
    }
}

// ================= GEMM2: h2[256 tile][64] = relu(bn1(h1)) @ W2 + b2, fused stats =================
__global__ void __launch_bounds__(256, 2) gemm2_kernel(const float* __restrict__ W, const float* __restrict__ b,
                                                       const float* __restrict__ gamma, const float* __restrict__ beta) {
    extern __shared__ __align__(16) float sm[];
    float* Ash = sm;              // [32][260]
    float* Wsh = sm + 32 * 260;   // [32][68]
    float* scs = Wsh + 32 * 68;   // [128]
    float* shs = scs + 128;       // [128]
    float* bsh = shs + 128;       // [64]
    int tid = threadIdx.x;
    int nb = blockIdx.x * 256;

    if (tid < 128) {
        float inv = 1.0f / (float)N_NODES;
        float mu = d_s1sum[tid] * inv;
        float var = d_s1sq[tid] * inv - mu * mu;
        float r = rsqrtf(var + 1e-5f);
        float sc = gamma[tid] * r;
        scs[tid] = sc; shs[tid] = beta[tid] - mu * sc;
    }
    if (tid < 64) bsh[tid] = b[tid];

    int warp = tid >> 5, lane = tid & 31;
    int wr = warp;
    int tr = lane >> 3, tc = lane & 7;
    int node0 = wr * 32 + tr * 8;
    int col0 = tc * 8;

    ull acc[8][4];
    __syncthreads();
    {
        float4 b0 = *(const float4*)&bsh[col0];
        float4 b1 = *(const float4*)&bsh[col0 + 4];
        ull i0 = pack2(b0.x, b0.y), i1 = pack2(b0.z, b0.w);
        ull i2 = pack2(b1.x, b1.y), i3 = pack2(b1.z, b1.w);
#pragma unroll
        for (int i = 0; i < 8; i++) { acc[i][0] = i0; acc[i][1] = i1; acc[i][2] = i2; acc[i][3] = i3; }
    }

    for (int kc = 0; kc < 4; kc++) {
        __syncthreads();
        for (int t = tid; t < 2048; t += 256) {
            int k = t >> 6, c = t & 63;
            Wsh[k * 68 + c] = W[(kc * 32 + k) * 64 + c];
        }
        for (int t = tid; t < 8192; t += 256) {
            int n = t >> 5, kk = t & 31;
            int gn = nb + n;
            float v = (gn < N_NODES) ? d_h1[(size_t)gn * 128 + kc * 32 + kk] : 0.f;
            Ash[kk * 260 + n] = fmaxf(fmaf(v, scs[kc * 32 + kk], shs[kc * 32 + kk]), 0.f);
        }
        __syncthreads();
#pragma unroll 8
        for (int k = 0; k < 32; k++) {
            float4 a0 = *(const float4*)&Ash[k * 260 + node0];
            float4 a1 = *(const float4*)&Ash[k * 260 + node0 + 4];
            ulonglong2 wA = *(const ulonglong2*)&Wsh[k * 68 + col0];
            ulonglong2 wB = *(const ulonglong2*)&Wsh[k * 68 + col0 + 4];
            float an[8] = {a0.x, a0.y, a0.z, a0.w, a1.x, a1.y, a1.z, a1.w};
#pragma unroll
            for (int i = 0; i < 8; i++) {
                ull ai = pack2(an[i], an[i]);
                fma2u(acc[i][0], ai, wA.x);
                fma2u(acc[i][1], ai, wA.y);
                fma2u(acc[i][2], ai, wB.x);
                fma2u(acc[i][3], ai, wB.y);
            }
        }
    }

    float csum[8] = {0,0,0,0,0,0,0,0}, csq[8] = {0,0,0,0,0,0,0,0};
#pragma unroll
    for (int i = 0; i < 8; i++) {
        int node = nb + node0 + i;
        if (node < N_NODES) {
            *(ulonglong2*)&d_h2[(size_t)node * HH + col0] = make_ulonglong2(acc[i][0], acc[i][1]);
            *(ulonglong2*)&d_h2[(size_t)node * HH + col0 + 4] = make_ulonglong2(acc[i][2], acc[i][3]);
#pragma unroll
            for (int j = 0; j < 4; j++) {
                float v0, v1; unpack2(acc[i][j], v0, v1);
                csum[2 * j] += v0; csq[2 * j] += v0 * v0;
                csum[2 * j + 1] += v1; csq[2 * j + 1] += v1 * v1;
            }
        }
    }
    __syncthreads();
    int g = wr * 4 + tr;  // 0..31
#pragma unroll
    for (int c = 0; c < 8; c++) {
        Ash[g * 132 + col0 + c] = csum[c];
        Ash[g * 132 + 64 + col0 + c] = csq[c];
    }
    __syncthreads();
    if (tid < 128) {
        float v = 0.f;
#pragma unroll
        for (int gg = 0; gg < 32; gg++) v += Ash[gg * 132 + tid];
        if (tid < 64) atomicAdd(&d_s2sum[tid], v);
        else atomicAdd(&d_s2sq[tid - 64], v);
    }
}

// BN2 (+relu), write z, z_cat slice, per-graph sums
__global__ void __launch_bounds__(512) finalize_kernel(const int* __restrict__ batch, float* __restrict__ out,
                                                       const float* __restrict__ gamma, const float* __restrict__ beta,
                                                       int l, int do_relu) {
    __shared__ float sred[8 * 64];
    __shared__ int sbounds[2];
    int g = blockIdx.x;
    int tid = threadIdx.x;
    int c = tid & 63, grp = tid >> 6;
    float inv = 1.0f / (float)N_NODES;
    float mu = d_s2sum[c] * inv;
    float var = d_s2sq[c] * inv - mu * mu;
    float r = rsqrtf(var + 1e-5f);
    float sc = gamma[c] * r;
    float sh = beta[c] - mu * sc;
    if (tid == 0) {
        int lo = 0, hi = N_NODES;
        while (lo < hi) { int m = (lo + hi) >> 1; if (batch[m] < g) lo = m + 1; else hi = m; }
        sbounds[0] = lo;
        hi = N_NODES;
        while (lo < hi) { int m = (lo + hi) >> 1; if (batch[m] <= g) lo = m + 1; else hi = m; }
        sbounds[1] = lo;
    }
    __syncthreads();
    int s = sbounds[0], e = sbounds[1];
    float acc = 0.f;
    for (int i = s + grp; i < e; i += 8) {
        float v = fmaf(d_h2[(size_t)i * HH + c], sc, sh);
        if (do_relu) v = fmaxf(v, 0.f);
        d_z[(size_t)i * HH + c] = v;
        out[(size_t)i * (NL * HH) + l * HH + c] = v;
        acc += v;
    }
    sred[grp * 64 + c] = acc;
    __syncthreads();
    if (grp == 0) {
        float tot = 0.f;
#pragma unroll
        for (int gg = 0; gg < 8; gg++) tot += sred[gg * 64 + c];
        out[(size_t)N_NODES * (NL * HH) + (size_t)g * (NL * HH) + l * HH + c] = tot;
    }
}

// ---------------- launch ----------------
extern "C" void kernel_launch(void* const* d_in, const int* in_sizes, int n_in,
                              void* d_out, int out_size) {
    const int*   x        = (const int*)d_in[0];
    const int*   ei       = (const int*)d_in[1];
    const int*   ea       = (const int*)d_in[2];
    const int*   batch    = (const int*)d_in[3];
    const float* atom_emb = (const float*)d_in[4];
    const float* bond_emb = (const float*)d_in[5];
    const float* W1       = (const float*)d_in[6];
    const float* b1       = (const float*)d_in[7];
    const float* gamma1   = (const float*)d_in[8];
    const float* beta1    = (const float*)d_in[9];
    const float* W2       = (const float*)d_in[10];
    const float* b2       = (const float*)d_in[11];
    const float* gbn      = (const float*)d_in[12];
    const float* bbn      = (const float*)d_in[13];
    float* out = (float*)d_out;

    const int SMEM1 = (64 * 132 * 2 + 128) * 4;                      // 68096
    const int SMEM2 = (32 * 260 + 32 * 68 + 128 + 128 + 64) * 4;     // 43264
    cudaFuncSetAttribute(gemm1_kernel, cudaFuncAttributeMaxDynamicSharedMemorySize, SMEM1);
    cudaFuncSetAttribute(gemm2_kernel, cudaFuncAttributeMaxDynamicSharedMemorySize, SMEM2);

    setup_kernel<<<30128, 256>>>(x, atom_emb, bond_emb, ei, ea);
    scan_kernel<<<1, 1024>>>();
    fill_kernel<<<5391, 256>>>(ei);

    int g1_blocks = (N_NODES + 127) / 128;   // 782
    int g2_blocks = (N_NODES + 255) / 256;   // 391
    for (int l = 0; l < NL; l++) {
        agg_kernel<<<N_NODES / 8, 256>>>();
        gemm1_kernel<<<g1_blocks, 256, SMEM1>>>(W1 + (size_t)l * 64 * 128, b1 + l * 128);
        gemm2_kernel<<<g2_blocks, 256, SMEM2>>>(W2 + (size_t)l * 128 * 64, b2 + l * 64,
                                                gamma1 + l * 128, beta1 + l * 128);
        finalize_kernel<<<N_GRAPHS, 512>>>(batch, out, gbn + l * HH, bbn + l * HH, l, (l != NL - 1) ? 1 : 0);
    }
}

// round 7
// speedup vs baseline: 1.1007x; 1.1007x over previous
#include <cuda_runtime.h>
#include <cuda_bf16.h>

#define N_NODES 100000
#define N_EDGES 1280000
#define HH 64
#define NL 5
#define N_GRAPHS 512

typedef unsigned long long ull;

// ---------------- static device scratch ----------------
__device__ __align__(16) float d_z[N_NODES * HH];
__device__ __align__(16) float d_hin[N_NODES * HH];
__device__ __align__(16) float d_h1[N_NODES * 128];
__device__ __align__(16) float d_h2[N_NODES * HH];
__device__ __align__(16) float d_tab[512 * HH];
__device__ int d_counts[N_NODES];            // statically zero; re-zeroed by fill each run
__device__ int d_rowstart[N_NODES + 1];
__device__ int d_cursor[N_NODES];
__device__ unsigned int d_csr_pack[N_EDGES]; // src | (code<<17)
__device__ unsigned short d_code[N_EDGES];
__device__ float d_s1sum[128], d_s1sq[128];
__device__ float d_s2sum[64],  d_s2sq[64];

// ---------------- packed f32x2 helpers ----------------
__device__ __forceinline__ ull pack2(float x, float y) {
    ull r; asm("mov.b64 %0, {%1, %2};" : "=l"(r) : "f"(x), "f"(y)); return r;
}
__device__ __forceinline__ void unpack2(ull v, float &x, float &y) {
    asm("mov.b64 {%0, %1}, %2;" : "=f"(x), "=f"(y) : "l"(v));
}
__device__ __forceinline__ void fma2u(ull &d, ull a, ull b) {
    asm("fma.rn.f32x2 %0, %1, %2, %0;" : "+l"(d) : "l"(a), "l"(b));
}

// ---------------- fused setup: z0 + bond table + degree count ----------------
__global__ void __launch_bounds__(256) setup_kernel(const int* __restrict__ x,
                                                    const float* __restrict__ atom_emb,
                                                    const float* __restrict__ bond_emb,
                                                    const int* __restrict__ ei,
                                                    const int* __restrict__ ea) {
    int bb = blockIdx.x;
    if (bb < 25000) {
        int t = bb * 256 + threadIdx.x;  // N*64
        int n = t >> 6, c = t & 63;
        float s = 0.f;
#pragma unroll
        for (int a = 0; a < 9; a++) {
            int idx = __ldg(&x[n * 9 + a]);
            s += __ldg(&atom_emb[(a * 128 + idx) * HH + c]);
        }
        d_z[t] = s;
    } else if (bb < 25128) {
        int t = (bb - 25000) * 256 + threadIdx.x;  // 512*64
        int q = t >> 6, c = t & 63;
        int a0 = q >> 6, a1 = (q >> 3) & 7, a2 = q & 7;
        d_tab[t] = bond_emb[a0 * HH + c] + bond_emb[(8 + a1) * HH + c] + bond_emb[(16 + a2) * HH + c];
    } else {
        int e = (bb - 25128) * 256 + threadIdx.x;  // N_EDGES
        int a0 = ea[e * 3 + 0], a1 = ea[e * 3 + 1], a2 = ea[e * 3 + 2];
        d_code[e] = (unsigned short)((a0 << 6) | (a1 << 3) | a2);
        atomicAdd(&d_counts[ei[N_EDGES + e]], 1);
    }
}

// single-block scan, 4 elements per thread per pass (25 passes)
__global__ void scan_kernel() {
    __shared__ int wsum[32];
    __shared__ int s_carry;
    int tid = threadIdx.x, lane = tid & 31, wid = tid >> 5;
    if (tid == 0) s_carry = 0;
    __syncthreads();
    for (int base = 0; base < N_NODES; base += 4096) {
        int i0 = base + tid * 4;
        int4 v = make_int4(0, 0, 0, 0);
        if (i0 + 3 < N_NODES) v = *(const int4*)&d_counts[i0];
        else {
            if (i0 + 0 < N_NODES) v.x = d_counts[i0 + 0];
            if (i0 + 1 < N_NODES) v.y = d_counts[i0 + 1];
            if (i0 + 2 < N_NODES) v.z = d_counts[i0 + 2];
            if (i0 + 3 < N_NODES) v.w = d_counts[i0 + 3];
        }
        int t0 = v.x, t1 = t0 + v.y, t2 = t1 + v.z, t3 = t2 + v.w;
        int xs = t3;
#pragma unroll
        for (int o = 1; o < 32; o <<= 1) { int y = __shfl_up_sync(0xffffffffu, xs, o); if (lane >= o) xs += y; }
        if (lane == 31) wsum[wid] = xs;
        __syncthreads();
        if (wid == 0) {
            int s = wsum[lane];
#pragma unroll
            for (int o = 1; o < 32; o <<= 1) { int y = __shfl_up_sync(0xffffffffu, s, o); if (lane >= o) s += y; }
            wsum[lane] = s;
        }
        __syncthreads();
        int warp_excl = (wid > 0) ? wsum[wid - 1] : 0;
        int carry = s_carry;
        int ex = carry + warp_excl + xs - t3;
        int4 rs = make_int4(ex, ex + t0, ex + t1, ex + t2);
        if (i0 + 3 < N_NODES) {
            *(int4*)&d_rowstart[i0] = rs;
            *(int4*)&d_cursor[i0] = rs;
        } else {
            if (i0 + 0 < N_NODES) { d_rowstart[i0 + 0] = rs.x; d_cursor[i0 + 0] = rs.x; }
            if (i0 + 1 < N_NODES) { d_rowstart[i0 + 1] = rs.y; d_cursor[i0 + 1] = rs.y; }
            if (i0 + 2 < N_NODES) { d_rowstart[i0 + 2] = rs.z; d_cursor[i0 + 2] = rs.z; }
            if (i0 + 3 < N_NODES) { d_rowstart[i0 + 3] = rs.w; d_cursor[i0 + 3] = rs.w; }
        }
        __syncthreads();
        if (tid == 1023) s_carry = carry + wsum[31];
        __syncthreads();
    }
    if (threadIdx.x == 0) d_rowstart[N_NODES] = s_carry;
}

// fill CSR (packed src|code<<17); trailing blocks re-zero d_counts for the NEXT execution
__global__ void fill_kernel(const int* __restrict__ ei) {
    int bb = blockIdx.x;
    if (bb < 5000) {
        int e = bb * 256 + threadIdx.x;
        int dst = ei[N_EDGES + e];
        int pos = atomicAdd(&d_cursor[dst], 1);
        d_csr_pack[pos] = (unsigned int)ei[e] | ((unsigned int)d_code[e] << 17);
    } else {
        int t = (bb - 5000) * 256 + threadIdx.x;
        if (t < N_NODES) d_counts[t] = 0;
    }
}

// ---------------- per-layer kernels ----------------
// half-warp per node: each 16-lane half walks its node's edge list directly.
// Per edge: 1 uniform LDG (packed), 1 LDG.128 z gather, 1 LDG.128 tab. No shfl.
__global__ void __launch_bounds__(256) agg_kernel() {
    if (blockIdx.x == 0) {
        int t = threadIdx.x;
        if (t < 128) { d_s1sum[t] = 0.f; d_s1sq[t] = 0.f; }
        else if (t < 192) { int c = t - 128; d_s2sum[c] = 0.f; d_s2sq[c] = 0.f; }
    }
    int warp_id = (blockIdx.x * blockDim.x + threadIdx.x) >> 5;
    int lane = threadIdx.x & 31;
    int half = lane >> 4, h = lane & 15;
    int node = warp_id * 2 + half;
    if (node >= N_NODES) return;
    float4 acc = make_float4(0.f, 0.f, 0.f, 0.f);
    int rs = d_rowstart[node], re = d_rowstart[node + 1];
    for (int k = rs; k < re; k++) {
        unsigned int v = __ldg(&d_csr_pack[k]);
        int s = (int)(v & 0x1FFFFu);
        int c = (int)(v >> 17);
        float4 zv = __ldg((const float4*)(d_z + (size_t)s * HH) + h);
        float4 tv = __ldg((const float4*)(d_tab + c * HH) + h);
        acc.x += fmaxf(zv.x + tv.x, 0.f);
        acc.y += fmaxf(zv.y + tv.y, 0.f);
        acc.z += fmaxf(zv.z + tv.z, 0.f);
        acc.w += fmaxf(zv.w + tv.w, 0.f);
    }
    float4 zme = __ldg((const float4*)(d_z + (size_t)node * HH) + h);
    acc.x += zme.x; acc.y += zme.y; acc.z += zme.z; acc.w += zme.w;
    ((float4*)(d_hin + (size_t)node * HH))[h] = acc;
}

// ================= GEMM1: h1[128 tile][128] = hin @ W1 + b1, fused col-stats =================
__global__ void __launch_bounds__(256, 2) gemm1_kernel(const float* __restrict__ W, const float* __restrict__ b) {
    extern __shared__ __align__(16) float sm[];
    float* Wsh = sm;             // [64][132]
    float* Ash = sm + 64 * 132;  // [64][132]
    float* bsh = Ash + 64 * 132; // [128]
    int tid = threadIdx.x;
    int nb = blockIdx.x * 128;

    for (int t = tid; t < 8192; t += 256) {
        int k = t >> 7, c = t & 127;
        Wsh[k * 132 + c] = W[t];
    }
    if (tid < 128) bsh[tid] = b[tid];
    for (int t = tid; t < 8192; t += 256) {
        int n = t >> 6, c = t & 63;
        int gn = nb + n;
        Ash[c * 132 + n] = (gn < N_NODES) ? d_hin[(size_t)gn * HH + c] : 0.f;
    }
    __syncthreads();

    int warp = tid >> 5, lane = tid & 31;
    int wr = warp >> 1, wc = warp & 1;
    int tr = lane >> 3, tc = lane & 7;
    int node0 = wr * 32 + tr * 8;
    int col0 = wc * 64 + tc * 8;

    ull acc[8][4];
    {
        float4 b0 = *(const float4*)&bsh[col0];
        float4 b1 = *(const float4*)&bsh[col0 + 4];
        ull i0 = pack2(b0.x, b0.y), i1 = pack2(b0.z, b0.w);
        ull i2 = pack2(b1.x, b1.y), i3 = pack2(b1.z, b1.w);
#pragma unroll
        for (int i = 0; i < 8; i++) { acc[i][0] = i0; acc[i][1] = i1; acc[i][2] = i2; acc[i][3] = i3; }
    }

#pragma unroll 8
    for (int k = 0; k < 64; k++) {
        float4 a0 = *(const float4*)&Ash[k * 132 + node0];
        float4 a1 = *(const float4*)&Ash[k * 132 + node0 + 4];
        ulonglong2 wA = *(const ulonglong2*)&Wsh[k * 132 + col0];
        ulonglong2 wB = *(const ulonglong2*)&Wsh[k * 132 + col0 + 4];
        float an[8] = {a0.x, a0.y, a0.z, a0.w, a1.x, a1.y, a1.z, a1.w};
#pragma unroll
        for (int i = 0; i < 8; i++) {
            ull ai = pack2(an[i], an[i]);
            fma2u(acc[i][0], ai, wA.x);
            fma2u(acc[i][1], ai, wA.y);
            fma2u(acc[i][2], ai, wB.x);
            fma2u(acc[i][3], ai, wB.y);
        }
    }

    float csum[8] = {0,0,0,0,0,0,0,0}, csq[8] = {0,0,0,0,0,0,0,0};
#pragma unroll
    for (int i = 0; i < 8; i++) {
        int node = nb + node0 + i;
        if (node < N_NODES) {
            *(ulonglong2*)&d_h1[(size_t)node * 128 + col0] = make_ulonglong2(acc[i][0], acc[i][1]);
            *(ulonglong2*)&d_h1[(size_t)node * 128 + col0 + 4] = make_ulonglong2(acc[i][2], acc[i][3]);
#pragma unroll
            for (int j = 0; j < 4; j++) {
                float v0, v1; unpack2(acc[i][j], v0, v1);
                csum[2 * j] += v0; csq[2 * j] += v0 * v0;
                csum[2 * j + 1] += v1; csq[2 * j + 1] += v1 * v1;
            }
        }
    }
    __syncthreads();
    int g = wr * 4 + tr;  // 0..15
#pragma unroll
    for (int c = 0; c < 8; c++) {
        Wsh[g * 264 + col0 + c] = csum[c];
        Wsh[g * 264 + 128 + col0 + c] = csq[c];
    }
    __syncthreads();
    {
        float v = 0.f;
#pragma unroll
        for (int gg = 0; gg < 16; gg++) v += Wsh[gg * 264 + tid];
        if (tid < 128) atomicAdd(&d_s1sum[tid], v);
        else atomicAdd(&d_s1sq[tid - 128], v);
    }
}

// ================= GEMM2: h2[256 tile][64] = relu(bn1(h1)) @ W2 + b2, fused stats =================
__global__ void __launch_bounds__(256, 2) gemm2_kernel(const float* __restrict__ W, const float* __restrict__ b,
                                                       const float* __restrict__ gamma, const float* __restrict__ beta) {
    extern __shared__ __align__(16) float sm[];
    float* Ash = sm;              // [32][260]
    float* Wsh = sm + 32 * 260;   // [32][68]
    float* scs = Wsh + 32 * 68;   // [128]
    float* shs = scs + 128;       // [128]
    float* bsh = shs + 128;       // [64]
    int tid = threadIdx.x;
    int nb = blockIdx.x * 256;

    if (tid < 128) {
        float inv = 1.0f / (float)N_NODES;
        float mu = d_s1sum[tid] * inv;
        float var = d_s1sq[tid] * inv - mu * mu;
        float r = rsqrtf(var + 1e-5f);
        float sc = gamma[tid] * r;
        scs[tid] = sc; shs[tid] = beta[tid] - mu * sc;
    }
    if (tid < 64) bsh[tid] = b[tid];

    int warp = tid >> 5, lane = tid & 31;
    int wr = warp;
    int tr = lane >> 3, tc = lane & 7;
    int node0 = wr * 32 + tr * 8;
    int col0 = tc * 8;

    ull acc[8][4];
    __syncthreads();
    {
        float4 b0 = *(const float4*)&bsh[col0];
        float4 b1 = *(const float4*)&bsh[col0 + 4];
        ull i0 = pack2(b0.x, b0.y), i1 = pack2(b0.z, b0.w);
        ull i2 = pack2(b1.x, b1.y), i3 = pack2(b1.z, b1.w);
#pragma unroll
        for (int i = 0; i < 8; i++) { acc[i][0] = i0; acc[i][1] = i1; acc[i][2] = i2; acc[i][3] = i3; }
    }

    for (int kc = 0; kc < 4; kc++) {
        __syncthreads();
        for (int t = tid; t < 2048; t += 256) {
            int k = t >> 6, c = t & 63;
            Wsh[k * 68 + c] = W[(kc * 32 + k) * 64 + c];
        }
        for (int t = tid; t < 8192; t += 256) {
            int n = t >> 5, kk = t & 31;
            int gn = nb + n;
            float v = (gn < N_NODES) ? d_h1[(size_t)gn * 128 + kc * 32 + kk] : 0.f;
            Ash[kk * 260 + n] = fmaxf(fmaf(v, scs[kc * 32 + kk], shs[kc * 32 + kk]), 0.f);
        }
        __syncthreads();
#pragma unroll 8
        for (int k = 0; k < 32; k++) {
            float4 a0 = *(const float4*)&Ash[k * 260 + node0];
            float4 a1 = *(const float4*)&Ash[k * 260 + node0 + 4];
            ulonglong2 wA = *(const ulonglong2*)&Wsh[k * 68 + col0];
            ulonglong2 wB = *(const ulonglong2*)&Wsh[k * 68 + col0 + 4];
            float an[8] = {a0.x, a0.y, a0.z, a0.w, a1.x, a1.y, a1.z, a1.w};
#pragma unroll
            for (int i = 0; i < 8; i++) {
                ull ai = pack2(an[i], an[i]);
                fma2u(acc[i][0], ai, wA.x);
                fma2u(acc[i][1], ai, wA.y);
                fma2u(acc[i][2], ai, wB.x);
                fma2u(acc[i][3], ai, wB.y);
            }
        }
    }

    float csum[8] = {0,0,0,0,0,0,0,0}, csq[8] = {0,0,0,0,0,0,0,0};
#pragma unroll
    for (int i = 0; i < 8; i++) {
        int node = nb + node0 + i;
        if (node < N_NODES) {
            *(ulonglong2*)&d_h2[(size_t)node * HH + col0] = make_ulonglong2(acc[i][0], acc[i][1]);
            *(ulonglong2*)&d_h2[(size_t)node * HH + col0 + 4] = make_ulonglong2(acc[i][2], acc[i][3]);
#pragma unroll
            for (int j = 0; j < 4; j++) {
                float v0, v1; unpack2(acc[i][j], v0, v1);
                csum[2 * j] += v0; csq[2 * j] += v0 * v0;
                csum[2 * j + 1] += v1; csq[2 * j + 1] += v1 * v1;
            }
        }
    }
    __syncthreads();
    int g = wr * 4 + tr;  // 0..31
#pragma unroll
    for (int c = 0; c < 8; c++) {
        Ash[g * 132 + col0 + c] = csum[c];
        Ash[g * 132 + 64 + col0 + c] = csq[c];
    }
    __syncthreads();
    if (tid < 128) {
        float v = 0.f;
#pragma unroll
        for (int gg = 0; gg < 32; gg++) v += Ash[gg * 132 + tid];
        if (tid < 64) atomicAdd(&d_s2sum[tid], v);
        else atomicAdd(&d_s2sq[tid - 64], v);
    }
}

// BN2 (+relu), write z, z_cat slice, per-graph sums
__global__ void __launch_bounds__(512) finalize_kernel(const int* __restrict__ batch, float* __restrict__ out,
                                                       const float* __restrict__ gamma, const float* __restrict__ beta,
                                                       int l, int do_relu) {
    __shared__ float sred[8 * 64];
    __shared__ int sbounds[2];
    int g = blockIdx.x;
    int tid = threadIdx.x;
    int c = tid & 63, grp = tid >> 6;
    float inv = 1.0f / (float)N_NODES;
    float mu = d_s2sum[c] * inv;
    float var = d_s2sq[c] * inv - mu * mu;
    float r = rsqrtf(var + 1e-5f);
    float sc = gamma[c] * r;
    float sh = beta[c] - mu * sc;
    if (tid == 0) {
        int lo = 0, hi = N_NODES;
        while (lo < hi) { int m = (lo + hi) >> 1; if (batch[m] < g) lo = m + 1; else hi = m; }
        sbounds[0] = lo;
        hi = N_NODES;
        while (lo < hi) { int m = (lo + hi) >> 1; if (batch[m] <= g) lo = m + 1; else hi = m; }
        sbounds[1] = lo;
    }
    __syncthreads();
    int s = sbounds[0], e = sbounds[1];
    float acc = 0.f;
    for (int i = s + grp; i < e; i += 8) {
        float v = fmaf(d_h2[(size_t)i * HH + c], sc, sh);
        if (do_relu) v = fmaxf(v, 0.f);
        d_z[(size_t)i * HH + c] = v;
        out[(size_t)i * (NL * HH) + l * HH + c] = v;
        acc += v;
    }
    sred[grp * 64 + c] = acc;
    __syncthreads();
    if (grp == 0) {
        float tot = 0.f;
#pragma unroll
        for (int gg = 0; gg < 8; gg++) tot += sred[gg * 64 + c];
        out[(size_t)N_NODES * (NL * HH) + (size_t)g * (NL * HH) + l * HH + c] = tot;
    }
}

// ---------------- launch ----------------
extern "C" void kernel_launch(void* const* d_in, const int* in_sizes, int n_in,
                              void* d_out, int out_size) {
    const int*   x        = (const int*)d_in[0];
    const int*   ei       = (const int*)d_in[1];
    const int*   ea       = (const int*)d_in[2];
    const int*   batch    = (const int*)d_in[3];
    const float* atom_emb = (const float*)d_in[4];
    const float* bond_emb = (const float*)d_in[5];
    const float* W1       = (const float*)d_in[6];
    const float* b1       = (const float*)d_in[7];
    const float* gamma1   = (const float*)d_in[8];
    const float* beta1    = (const float*)d_in[9];
    const float* W2       = (const float*)d_in[10];
    const float* b2       = (const float*)d_in[11];
    const float* gbn      = (const float*)d_in[12];
    const float* bbn      = (const float*)d_in[13];
    float* out = (float*)d_out;

    const int SMEM1 = (64 * 132 * 2 + 128) * 4;                      // 68096
    const int SMEM2 = (32 * 260 + 32 * 68 + 128 + 128 + 64) * 4;     // 43264
    cudaFuncSetAttribute(gemm1_kernel, cudaFuncAttributeMaxDynamicSharedMemorySize, SMEM1);
    cudaFuncSetAttribute(gemm2_kernel, cudaFuncAttributeMaxDynamicSharedMemorySize, SMEM2);

    setup_kernel<<<30128, 256>>>(x, atom_emb, bond_emb, ei, ea);
    scan_kernel<<<1, 1024>>>();
    fill_kernel<<<5391, 256>>>(ei);

    int g1_blocks = (N_NODES + 127) / 128;   // 782
    int g2_blocks = (N_NODES + 255) / 256;   // 391
    int agg_blocks = (N_NODES / 2 + 7) / 8;  // 6250 (8 warps/block, 2 nodes/warp)
    for (int l = 0; l < NL; l++) {
        agg_kernel<<<agg_blocks, 256>>>();
        gemm1_kernel<<<g1_blocks, 256, SMEM1>>>(W1 + (size_t)l * 64 * 128, b1 + l * 128);
        gemm2_kernel<<<g2_blocks, 256, SMEM2>>>(W2 + (size_t)l * 128 * 64, b2 + l * 64,
                                                gamma1 + l * 128, beta1 + l * 128);
        finalize_kernel<<<N_GRAPHS, 512>>>(batch, out, gbn + l * HH, bbn + l * HH, l, (l != NL - 1) ? 1 : 0);
    }
}

// round 8
// speedup vs baseline: 1.1102x; 1.0086x over previous
#include <cuda_runtime.h>
#include <cuda_bf16.h>

#define N_NODES 100000
#define N_EDGES 1280000
#define HH 64
#define NL 5
#define N_GRAPHS 512

typedef unsigned long long ull;

// ---------------- static device scratch ----------------
__device__ __align__(16) float d_z[N_NODES * HH];
__device__ __align__(16) float d_hin[N_NODES * HH];
__device__ __align__(16) float d_h1[N_NODES * 128];
__device__ __align__(16) float d_h2[N_NODES * HH];
__device__ __align__(16) float d_tab[512 * HH];
__device__ int d_counts[N_NODES];            // statically zero; re-zeroed by fill each run
__device__ int d_rowstart[N_NODES + 1];
__device__ int d_cursor[N_NODES];
__device__ unsigned int d_csr_pack[N_EDGES]; // src | (code<<17)
__device__ unsigned short d_code[N_EDGES];
__device__ float d_s1sum[128], d_s1sq[128];
__device__ float d_s2sum[64],  d_s2sq[64];

// ---------------- packed f32x2 helpers ----------------
__device__ __forceinline__ ull pack2(float x, float y) {
    ull r; asm("mov.b64 %0, {%1, %2};" : "=l"(r) : "f"(x), "f"(y)); return r;
}
__device__ __forceinline__ void unpack2(ull v, float &x, float &y) {
    asm("mov.b64 {%0, %1}, %2;" : "=f"(x), "=f"(y) : "l"(v));
}
__device__ __forceinline__ void fma2u(ull &d, ull a, ull b) {
    asm("fma.rn.f32x2 %0, %1, %2, %0;" : "+l"(d) : "l"(a), "l"(b));
}

// ---------------- fused setup: z0 + bond table + degree count ----------------
__global__ void __launch_bounds__(256) setup_kernel(const int* __restrict__ x,
                                                    const float* __restrict__ atom_emb,
                                                    const float* __restrict__ bond_emb,
                                                    const int* __restrict__ ei,
                                                    const int* __restrict__ ea) {
    int bb = blockIdx.x;
    if (bb < 25000) {
        int t = bb * 256 + threadIdx.x;  // N*64
        int n = t >> 6, c = t & 63;
        float s = 0.f;
#pragma unroll
        for (int a = 0; a < 9; a++) {
            int idx = __ldg(&x[n * 9 + a]);
            s += __ldg(&atom_emb[(a * 128 + idx) * HH + c]);
        }
        d_z[t] = s;
    } else if (bb < 25128) {
        int t = (bb - 25000) * 256 + threadIdx.x;  // 512*64
        int q = t >> 6, c = t & 63;
        int a0 = q >> 6, a1 = (q >> 3) & 7, a2 = q & 7;
        d_tab[t] = bond_emb[a0 * HH + c] + bond_emb[(8 + a1) * HH + c] + bond_emb[(16 + a2) * HH + c];
    } else {
        int e = (bb - 25128) * 256 + threadIdx.x;  // N_EDGES
        int a0 = ea[e * 3 + 0], a1 = ea[e * 3 + 1], a2 = ea[e * 3 + 2];
        d_code[e] = (unsigned short)((a0 << 6) | (a1 << 3) | a2);
        atomicAdd(&d_counts[ei[N_EDGES + e]], 1);
    }
}

// single-block scan, 4 elements per thread per pass (25 passes)
__global__ void scan_kernel() {
    __shared__ int wsum[32];
    __shared__ int s_carry;
    int tid = threadIdx.x, lane = tid & 31, wid = tid >> 5;
    if (tid == 0) s_carry = 0;
    __syncthreads();
    for (int base = 0; base < N_NODES; base += 4096) {
        int i0 = base + tid * 4;
        int4 v = make_int4(0, 0, 0, 0);
        if (i0 + 3 < N_NODES) v = *(const int4*)&d_counts[i0];
        else {
            if (i0 + 0 < N_NODES) v.x = d_counts[i0 + 0];
            if (i0 + 1 < N_NODES) v.y = d_counts[i0 + 1];
            if (i0 + 2 < N_NODES) v.z = d_counts[i0 + 2];
            if (i0 + 3 < N_NODES) v.w = d_counts[i0 + 3];
        }
        int t0 = v.x, t1 = t0 + v.y, t2 = t1 + v.z, t3 = t2 + v.w;
        int xs = t3;
#pragma unroll
        for (int o = 1; o < 32; o <<= 1) { int y = __shfl_up_sync(0xffffffffu, xs, o); if (lane >= o) xs += y; }
        if (lane == 31) wsum[wid] = xs;
        __syncthreads();
        if (wid == 0) {
            int s = wsum[lane];
#pragma unroll
            for (int o = 1; o < 32; o <<= 1) { int y = __shfl_up_sync(0xffffffffu, s, o); if (lane >= o) s += y; }
            wsum[lane] = s;
        }
        __syncthreads();
        int warp_excl = (wid > 0) ? wsum[wid - 1] : 0;
        int carry = s_carry;
        int ex = carry + warp_excl + xs - t3;
        int4 rs = make_int4(ex, ex + t0, ex + t1, ex + t2);
        if (i0 + 3 < N_NODES) {
            *(int4*)&d_rowstart[i0] = rs;
            *(int4*)&d_cursor[i0] = rs;
        } else {
            if (i0 + 0 < N_NODES) { d_rowstart[i0 + 0] = rs.x; d_cursor[i0 + 0] = rs.x; }
            if (i0 + 1 < N_NODES) { d_rowstart[i0 + 1] = rs.y; d_cursor[i0 + 1] = rs.y; }
            if (i0 + 2 < N_NODES) { d_rowstart[i0 + 2] = rs.z; d_cursor[i0 + 2] = rs.z; }
            if (i0 + 3 < N_NODES) { d_rowstart[i0 + 3] = rs.w; d_cursor[i0 + 3] = rs.w; }
        }
        __syncthreads();
        if (tid == 1023) s_carry = carry + wsum[31];
        __syncthreads();
    }
    if (threadIdx.x == 0) d_rowstart[N_NODES] = s_carry;
}

// fill CSR (packed src|code<<17); trailing blocks re-zero d_counts for the NEXT execution
__global__ void fill_kernel(const int* __restrict__ ei) {
    int bb = blockIdx.x;
    if (bb < 5000) {
        int e = bb * 256 + threadIdx.x;
        int dst = ei[N_EDGES + e];
        int pos = atomicAdd(&d_cursor[dst], 1);
        d_csr_pack[pos] = (unsigned int)ei[e] | ((unsigned int)d_code[e] << 17);
    } else {
        int t = (bb - 5000) * 256 + threadIdx.x;
        if (t < N_NODES) d_counts[t] = 0;
    }
}

// ---------------- per-layer kernels ----------------
// half-warp per node: each 16-lane half walks its node's edge list directly.
// Per edge: 1 uniform LDG (packed), 1 LDG.128 z gather, 1 LDG.128 tab. No shfl.
__global__ void __launch_bounds__(256) agg_kernel() {
    if (blockIdx.x == 0) {
        int t = threadIdx.x;
        if (t < 128) { d_s1sum[t] = 0.f; d_s1sq[t] = 0.f; }
        else if (t < 192) { int c = t - 128; d_s2sum[c] = 0.f; d_s2sq[c] = 0.f; }
    }
    int warp_id = (blockIdx.x * blockDim.x + threadIdx.x) >> 5;
    int lane = threadIdx.x & 31;
    int half = lane >> 4, h = lane & 15;
    int node = warp_id * 2 + half;
    if (node >= N_NODES) return;
    float4 acc = make_float4(0.f, 0.f, 0.f, 0.f);
    int rs = d_rowstart[node], re = d_rowstart[node + 1];
    for (int k = rs; k < re; k++) {
        unsigned int v = __ldg(&d_csr_pack[k]);
        int s = (int)(v & 0x1FFFFu);
        int c = (int)(v >> 17);
        float4 zv = __ldg((const float4*)(d_z + (size_t)s * HH) + h);
        float4 tv = __ldg((const float4*)(d_tab + c * HH) + h);
        acc.x += fmaxf(zv.x + tv.x, 0.f);
        acc.y += fmaxf(zv.y + tv.y, 0.f);
        acc.z += fmaxf(zv.z + tv.z, 0.f);
        acc.w += fmaxf(zv.w + tv.w, 0.f);
    }
    float4 zme = __ldg((const float4*)(d_z + (size_t)node * HH) + h);
    acc.x += zme.x; acc.y += zme.y; acc.z += zme.z; acc.w += zme.w;
    ((float4*)(d_hin + (size_t)node * HH))[h] = acc;
}

// ================= GEMM1: h1[128 tile][128] = hin @ W1 + b1, fused col-stats =================
__global__ void __launch_bounds__(256, 2) gemm1_kernel(const float* __restrict__ W, const float* __restrict__ b) {
    extern __shared__ __align__(16) float sm[];
    float* Wsh = sm;             // [64][132]
    float* Ash = sm + 64 * 132;  // [64][132]
    float* bsh = Ash + 64 * 132; // [128]
    int tid = threadIdx.x;
    int nb = blockIdx.x * 128;

    for (int t = tid; t < 8192; t += 256) {
        int k = t >> 7, c = t & 127;
        Wsh[k * 132 + c] = W[t];
    }
    if (tid < 128) bsh[tid] = b[tid];
    for (int t = tid; t < 8192; t += 256) {
        int n = t >> 6, c = t & 63;
        int gn = nb + n;
        Ash[c * 132 + n] = (gn < N_NODES) ? d_hin[(size_t)gn * HH + c] : 0.f;
    }
    __syncthreads();

    int warp = tid >> 5, lane = tid & 31;
    int wr = warp >> 1, wc = warp & 1;
    int tr = lane >> 3, tc = lane & 7;
    int node0 = wr * 32 + tr * 8;
    int col0 = wc * 64 + tc * 8;

    ull acc[8][4];
    {
        float4 b0 = *(const float4*)&bsh[col0];
        float4 b1 = *(const float4*)&bsh[col0 + 4];
        ull i0 = pack2(b0.x, b0.y), i1 = pack2(b0.z, b0.w);
        ull i2 = pack2(b1.x, b1.y), i3 = pack2(b1.z, b1.w);
#pragma unroll
        for (int i = 0; i < 8; i++) { acc[i][0] = i0; acc[i][1] = i1; acc[i][2] = i2; acc[i][3] = i3; }
    }

#pragma unroll 8
    for (int k = 0; k < 64; k++) {
        float4 a0 = *(const float4*)&Ash[k * 132 + node0];
        float4 a1 = *(const float4*)&Ash[k * 132 + node0 + 4];
        ulonglong2 wA = *(const ulonglong2*)&Wsh[k * 132 + col0];
        ulonglong2 wB = *(const ulonglong2*)&Wsh[k * 132 + col0 + 4];
        float an[8] = {a0.x, a0.y, a0.z, a0.w, a1.x, a1.y, a1.z, a1.w};
#pragma unroll
        for (int i = 0; i < 8; i++) {
            ull ai = pack2(an[i], an[i]);
            fma2u(acc[i][0], ai, wA.x);
            fma2u(acc[i][1], ai, wA.y);
            fma2u(acc[i][2], ai, wB.x);
            fma2u(acc[i][3], ai, wB.y);
        }
    }

    float csum[8] = {0,0,0,0,0,0,0,0}, csq[8] = {0,0,0,0,0,0,0,0};
#pragma unroll
    for (int i = 0; i < 8; i++) {
        int node = nb + node0 + i;
        if (node < N_NODES) {
            *(ulonglong2*)&d_h1[(size_t)node * 128 + col0] = make_ulonglong2(acc[i][0], acc[i][1]);
            *(ulonglong2*)&d_h1[(size_t)node * 128 + col0 + 4] = make_ulonglong2(acc[i][2], acc[i][3]);
#pragma unroll
            for (int j = 0; j < 4; j++) {
                float v0, v1; unpack2(acc[i][j], v0, v1);
                csum[2 * j] += v0; csq[2 * j] += v0 * v0;
                csum[2 * j + 1] += v1; csq[2 * j + 1] += v1 * v1;
            }
        }
    }
    __syncthreads();
    int g = wr * 4 + tr;  // 0..15
#pragma unroll
    for (int c = 0; c < 8; c++) {
        Wsh[g * 264 + col0 + c] = csum[c];
        Wsh[g * 264 + 128 + col0 + c] = csq[c];
    }
    __syncthreads();
    {
        float v = 0.f;
#pragma unroll
        for (int gg = 0; gg < 16; gg++) v += Wsh[gg * 264 + tid];
        if (tid < 128) atomicAdd(&d_s1sum[tid], v);
        else atomicAdd(&d_s1sq[tid - 128], v);
    }
}

// ================= GEMM2: h2[256 tile][64] = relu(bn1(h1)) @ W2 + b2, fused stats =================
__global__ void __launch_bounds__(256, 2) gemm2_kernel(const float* __restrict__ W, const float* __restrict__ b,
                                                       const float* __restrict__ gamma, const float* __restrict__ beta) {
    extern __shared__ __align__(16) float sm[];
    float* Ash = sm;              // [32][260]
    float* Wsh = sm + 32 * 260;   // [32][68]
    float* scs = Wsh + 32 * 68;   // [128]
    float* shs = scs + 128;       // [128]
    float* bsh = shs + 128;       // [64]
    int tid = threadIdx.x;
    int nb = blockIdx.x * 256;

    if (tid < 128) {
        float inv = 1.0f / (float)N_NODES;
        float mu = d_s1sum[tid] * inv;
        float var = d_s1sq[tid] * inv - mu * mu;
        float r = rsqrtf(var + 1e-5f);
        float sc = gamma[tid] * r;
        scs[tid] = sc; shs[tid] = beta[tid] - mu * sc;
    }
    if (tid < 64) bsh[tid] = b[tid];

    int warp = tid >> 5, lane = tid & 31;
    int wr = warp;
    int tr = lane >> 3, tc = lane & 7;
    int node0 = wr * 32 + tr * 8;
    int col0 = tc * 8;

    ull acc[8][4];
    __syncthreads();
    {
        float4 b0 = *(const float4*)&bsh[col0];
        float4 b1 = *(const float4*)&bsh[col0 + 4];
        ull i0 = pack2(b0.x, b0.y), i1 = pack2(b0.z, b0.w);
        ull i2 = pack2(b1.x, b1.y), i3 = pack2(b1.z, b1.w);
#pragma unroll
        for (int i = 0; i < 8; i++) { acc[i][0] = i0; acc[i][1] = i1; acc[i][2] = i2; acc[i][3] = i3; }
    }

    for (int kc = 0; kc < 4; kc++) {
        __syncthreads();
        for (int t = tid; t < 2048; t += 256) {
            int k = t >> 6, c = t & 63;
            Wsh[k * 68 + c] = W[(kc * 32 + k) * 64 + c];
        }
        for (int t = tid; t < 8192; t += 256) {
            int n = t >> 5, kk = t & 31;
            int gn = nb + n;
            float v = (gn < N_NODES) ? d_h1[(size_t)gn * 128 + kc * 32 + kk] : 0.f;
            Ash[kk * 260 + n] = fmaxf(fmaf(v, scs[kc * 32 + kk], shs[kc * 32 + kk]), 0.f);
        }
        __syncthreads();
#pragma unroll 8
        for (int k = 0; k < 32; k++) {
            float4 a0 = *(const float4*)&Ash[k * 260 + node0];
            float4 a1 = *(const float4*)&Ash[k * 260 + node0 + 4];
            ulonglong2 wA = *(const ulonglong2*)&Wsh[k * 68 + col0];
            ulonglong2 wB = *(const ulonglong2*)&Wsh[k * 68 + col0 + 4];
            float an[8] = {a0.x, a0.y, a0.z, a0.w, a1.x, a1.y, a1.z, a1.w};
#pragma unroll
            for (int i = 0; i < 8; i++) {
                ull ai = pack2(an[i], an[i]);
                fma2u(acc[i][0], ai, wA.x);
                fma2u(acc[i][1], ai, wA.y);
                fma2u(acc[i][2], ai, wB.x);
                fma2u(acc[i][3], ai, wB.y);
            }
        }
    }

    float csum[8] = {0,0,0,0,0,0,0,0}, csq[8] = {0,0,0,0,0,0,0,0};
#pragma unroll
    for (int i = 0; i < 8; i++) {
        int node = nb + node0 + i;
        if (node < N_NODES) {
            *(ulonglong2*)&d_h2[(size_t)node * HH + col0] = make_ulonglong2(acc[i][0], acc[i][1]);
            *(ulonglong2*)&d_h2[(size_t)node * HH + col0 + 4] = make_ulonglong2(acc[i][2], acc[i][3]);
#pragma unroll
            for (int j = 0; j < 4; j++) {
                float v0, v1; unpack2(acc[i][j], v0, v1);
                csum[2 * j] += v0; csq[2 * j] += v0 * v0;
                csum[2 * j + 1] += v1; csq[2 * j + 1] += v1 * v1;
            }
        }
    }
    __syncthreads();
    int g = wr * 4 + tr;  // 0..31
#pragma unroll
    for (int c = 0; c < 8; c++) {
        Ash[g * 132 + col0 + c] = csum[c];
        Ash[g * 132 + 64 + col0 + c] = csq[c];
    }
    __syncthreads();
    if (tid < 128) {
        float v = 0.f;
#pragma unroll
        for (int gg = 0; gg < 32; gg++) v += Ash[gg * 132 + tid];
        if (tid < 64) atomicAdd(&d_s2sum[tid], v);
        else atomicAdd(&d_s2sq[tid - 64], v);
    }
}

// BN2 (+relu), write z, z_cat slice, per-graph sums
__global__ void __launch_bounds__(512) finalize_kernel(const int* __restrict__ batch, float* __restrict__ out,
                                                       const float* __restrict__ gamma, const float* __restrict__ beta,
                                                       int l, int do_relu) {
    __shared__ float sred[8 * 64];
    __shared__ int sbounds[2];
    int g = blockIdx.x;
    int tid = threadIdx.x;
    int c = tid & 63, grp = tid >> 6;
    float inv = 1.0f / (float)N_NODES;
    float mu = d_s2sum[c] * inv;
    float var = d_s2sq[c] * inv - mu * mu;
    float r = rsqrtf(var + 1e-5f);
    float sc = gamma[c] * r;
    float sh = beta[c] - mu * sc;
    if (tid == 0) {
        int lo = 0, hi = N_NODES;
        while (lo < hi) { int m = (lo + hi) >> 1; if (batch[m] < g) lo = m + 1; else hi = m; }
        sbounds[0] = lo;
        hi = N_NODES;
        while (lo < hi) { int m = (lo + hi) >> 1; if (batch[m] <= g) lo = m + 1; else hi = m; }
        sbounds[1] = lo;
    }
    __syncthreads();
    int s = sbounds[0], e = sbounds[1];
    float acc = 0.f;
    for (int i = s + grp; i < e; i += 8) {
        float v = fmaf(d_h2[(size_t)i * HH + c], sc, sh);
        if (do_relu) v = fmaxf(v, 0.f);
        d_z[(size_t)i * HH + c] = v;
        out[(size_t)i * (NL * HH) + l * HH + c] = v;
        acc += v;
    }
    sred[grp * 64 + c] = acc;
    __syncthreads();
    if (grp == 0) {
        float tot = 0.f;
#pragma unroll
        for (int gg = 0; gg < 8; gg++) tot += sred[gg * 64 + c];
        out[(size_t)N_NODES * (NL * HH) + (size_t)g * (NL * HH) + l * HH + c] = tot;
    }
}

// ---------------- launch ----------------
extern "C" void kernel_launch(void* const* d_in, const int* in_sizes, int n_in,
                              void* d_out, int out_size) {
    const int*   x        = (const int*)d_in[0];
    const int*   ei       = (const int*)d_in[1];
    const int*   ea       = (const int*)d_in[2];
    const int*   batch    = (const int*)d_in[3];
    const float* atom_emb = (const float*)d_in[4];
    const float* bond_emb = (const float*)d_in[5];
    const float* W1       = (const float*)d_in[6];
    const float* b1       = (const float*)d_in[7];
    const float* gamma1   = (const float*)d_in[8];
    const float* beta1    = (const float*)d_in[9];
    const float* W2       = (const float*)d_in[10];
    const float* b2       = (const float*)d_in[11];
    const float* gbn      = (const float*)d_in[12];
    const float* bbn      = (const float*)d_in[13];
    float* out = (float*)d_out;

    const int SMEM1 = (64 * 132 * 2 + 128) * 4;                      // 68096
    const int SMEM2 = (32 * 260 + 32 * 68 + 128 + 128 + 64) * 4;     // 43264
    cudaFuncSetAttribute(gemm1_kernel, cudaFuncAttributeMaxDynamicSharedMemorySize, SMEM1);
    cudaFuncSetAttribute(gemm2_kernel, cudaFuncAttributeMaxDynamicSharedMemorySize, SMEM2);

    setup_kernel<<<30128, 256>>>(x, atom_emb, bond_emb, ei, ea);
    scan_kernel<<<1, 1024>>>();
    fill_kernel<<<5391, 256>>>(ei);

    int g1_blocks = (N_NODES + 127) / 128;   // 782
    int g2_blocks = (N_NODES + 255) / 256;   // 391
    int agg_blocks = (N_NODES / 2 + 7) / 8;  // 6250 (8 warps/block, 2 nodes/warp)
    for (int l = 0; l < NL; l++) {
        agg_kernel<<<agg_blocks, 256>>>();
        gemm1_kernel<<<g1_blocks, 256, SMEM1>>>(W1 + (size_t)l * 64 * 128, b1 + l * 128);
        gemm2_kernel<<<g2_blocks, 256, SMEM2>>>(W2 + (size_t)l * 128 * 64, b2 + l * 64,
                                                gamma1 + l * 128, beta1 + l * 128);
        finalize_kernel<<<N_GRAPHS, 512>>>(batch, out, gbn + l * HH, bbn + l * HH, l, (l != NL - 1) ? 1 : 0);
    }
}